// round 15
// baseline (speedup 1.0000x reference)
#include <cuda_runtime.h>
#include <cuda_fp16.h>
#include <math_constants.h>
#include <cstdint>

#define BB 8
#define NN 2048
#define DD 256
#define HH 16
#define KTOP 8

typedef unsigned long long u64;

// ---- scratch (static device globals; no allocation allowed) ----
__device__ unsigned short g_f1hi[BB * NN * DD];   // fp16 hi of f1n (B)
__device__ unsigned short g_f1lo[BB * NN * DD];   // fp16 lo of f1n (B)
__device__ unsigned short g_f2hi[BB * NN * DD];   // fp16 hi of f2n (A)
__device__ unsigned short g_f2lo[BB * NN * DD];   // fp16 lo of f2n (A)
__device__ float4 g_q4[BB * NN];         // (x,y,z,|q|^2)
__device__ float4 g_p4[BB * NN];         // (x,y,z,|p|^2)
__device__ float  g_tilemax[BB * NN * 32];  // per-row per-64col-tile max of w

// ======================= helpers =======================
__device__ __forceinline__ uint32_t smem_u32(const void* p) {
    uint32_t a;
    asm("{ .reg .u64 t; cvta.to.shared.u64 t, %1; cvt.u32.u64 %0, t; }"
        : "=r"(a) : "l"(p));
    return a;
}

// ---- packed f32x2 helpers ----
__device__ __forceinline__ u64 pack_dup(float x) {
    u64 r; asm("mov.b64 %0, {%1, %1};" : "=l"(r) : "f"(x)); return r;
}
__device__ __forceinline__ u64 pack2(float lo, float hi) {
    u64 r; asm("mov.b64 %0, {%1, %2};" : "=l"(r) : "f"(lo), "f"(hi)); return r;
}
__device__ __forceinline__ void unpack2(u64 v, float& lo, float& hi) {
    asm("mov.b64 {%0, %1}, %2;" : "=f"(lo), "=f"(hi) : "l"(v));
}
__device__ __forceinline__ u64 ffma2r(u64 a, u64 b, u64 c) {
    u64 d; asm("fma.rn.f32x2 %0, %1, %2, %3;" : "=l"(d) : "l"(a), "l"(b), "l"(c));
    return d;
}
__device__ __forceinline__ u64 mul2(u64 a, u64 b) {
    u64 d; asm("mul.rn.f32x2 %0, %1, %2;" : "=l"(d) : "l"(a), "l"(b)); return d;
}
__device__ __forceinline__ u64 add2(u64 a, u64 b) {
    u64 d; asm("add.rn.f32x2 %0, %1, %2;" : "=l"(d) : "l"(a), "l"(b)); return d;
}
#define ABSM 0x7FFFFFFF7FFFFFFFULL

// ---- legacy tensor-core primitives (sm_80+ baseline PTX) ----
#define LDSM4(R, A) \
    asm volatile("ldmatrix.sync.aligned.m8n8.x4.shared.b16 {%0,%1,%2,%3}, [%4];" \
        : "=r"((R)[0]), "=r"((R)[1]), "=r"((R)[2]), "=r"((R)[3]) : "r"(A))

#define MMA16816H(C, A, B0, B1) \
    asm volatile("mma.sync.aligned.m16n8k16.row.col.f32.f16.f16.f32 " \
        "{%0,%1,%2,%3},{%4,%5,%6,%7},{%8,%9},{%0,%1,%2,%3};" \
        : "+f"((C)[0]), "+f"((C)[1]), "+f"((C)[2]), "+f"((C)[3]) \
        : "r"((A)[0]), "r"((A)[1]), "r"((A)[2]), "r"((A)[3]), "r"(B0), "r"(B1))

// ---------------------------------------------------------------
// K1a/K1b: normalize rows of one tensor to fp16 hi/lo pairs
// ---------------------------------------------------------------
__device__ __forceinline__ void norm_body(const float* __restrict__ src,
                                          unsigned short* dh, unsigned short* dl)
{
    int r = (blockIdx.x * blockDim.x + threadIdx.x) >> 5;
    int lane = threadIdx.x & 31;

    const float4* x = (const float4*)(src + (size_t)r * DD);
    float4 a = x[lane];
    float4 c = x[lane + 32];
    float ss = a.x * a.x + a.y * a.y + a.z * a.z + a.w * a.w
             + c.x * c.x + c.y * c.y + c.z * c.z + c.w * c.w;
#pragma unroll
    for (int o = 16; o; o >>= 1) ss += __shfl_xor_sync(0xffffffffu, ss, o);
    float inv = 1.0f / (sqrtf(ss) + 1e-8f);

    float va[8] = { a.x * inv, a.y * inv, a.z * inv, a.w * inv,
                    c.x * inv, c.y * inv, c.z * inv, c.w * inv };
    unsigned short hi[8], lo[8];
#pragma unroll
    for (int i = 0; i < 8; ++i) {
        __half hh = __float2half_rn(va[i]);
        hi[i] = __half_as_ushort(hh);
        lo[i] = __half_as_ushort(__float2half_rn(va[i] - __half2float(hh)));
    }

    uint2* oh = (uint2*)(dh + (size_t)r * DD);
    uint2* ol = (uint2*)(dl + (size_t)r * DD);
    oh[lane]      = make_uint2((uint32_t)hi[0] | ((uint32_t)hi[1] << 16),
                               (uint32_t)hi[2] | ((uint32_t)hi[3] << 16));
    oh[lane + 32] = make_uint2((uint32_t)hi[4] | ((uint32_t)hi[5] << 16),
                               (uint32_t)hi[6] | ((uint32_t)hi[7] << 16));
    ol[lane]      = make_uint2((uint32_t)lo[0] | ((uint32_t)lo[1] << 16),
                               (uint32_t)lo[2] | ((uint32_t)lo[3] << 16));
    ol[lane + 32] = make_uint2((uint32_t)lo[4] | ((uint32_t)lo[5] << 16),
                               (uint32_t)lo[6] | ((uint32_t)lo[7] << 16));
}

__global__ void prep_f1_kernel(const float* __restrict__ f1)
{ norm_body(f1, g_f1hi, g_f1lo); }

__global__ void prep_f2_kernel(const float* __restrict__ f2)
{ norm_body(f2, g_f2hi, g_f2lo); }

__global__ void prep_coord_kernel(const float* __restrict__ p,
                                  const float* __restrict__ q)
{
    int t = blockIdx.x * blockDim.x + threadIdx.x;
    if (t < BB * NN) {
        float px = p[t * 3 + 0], py = p[t * 3 + 1], pz = p[t * 3 + 2];
        g_p4[t] = make_float4(px, py, pz, px * px + py * py + pz * pz);
        float qx = q[t * 3 + 0], qy = q[t * 3 + 1], qz = q[t * 3 + 2];
        g_q4[t] = make_float4(qx, qy, qz, qx * qx + qy * qy + qz * qz);
    }
}

// ---------------------------------------------------------------
// K2: mma.sync fp16 3-term GEMM + packed MLP (R13 epilogue) + tile-max
// ---------------------------------------------------------------
#define TS     10240          // one tile: 128 rows * 80B
#define BUFSZ  40960          // 4 tiles (Ahi,Alo,Bhi,Blo)
#define OFF_QC 81920
#define OFF_PX 83968
#define OFF_PY 84480
#define OFF_PZ 84992
#define OFF_PW 85504
#define SM_TOTAL 86016

__global__ void __launch_bounds__(256, 1)
w_kernel(const float* __restrict__ W1, const float* __restrict__ b1,
         const float* __restrict__ W2, const float* __restrict__ b2,
         float* __restrict__ out_w)
{
    extern __shared__ __align__(1024) unsigned char smem[];
    const uint32_t sb = smem_u32(smem);
    const int tid = threadIdx.x, wid = tid >> 5, lane = tid & 31;
    const int warp_m = wid & 3, warp_n = wid >> 2;
    const int b = blockIdx.z, q0 = blockIdx.y * 128, p0 = blockIdx.x * 128;

    if (tid < 128) {
        ((float4*)(smem + OFF_QC))[tid] = g_q4[b * NN + q0 + tid];
    } else {
        int t = tid - 128;
        float4 pv = g_p4[b * NN + p0 + t];
        ((float*)(smem + OFF_PX))[t] = pv.x;
        ((float*)(smem + OFF_PY))[t] = pv.y;
        ((float*)(smem + OFF_PZ))[t] = pv.z;
        ((float*)(smem + OFF_PW))[t] = pv.w;
    }

    const uint4* srcs[4] = {
        ((const uint4*)g_f2hi) + (size_t)(b * NN + q0) * 32,   // A hi
        ((const uint4*)g_f2lo) + (size_t)(b * NN + q0) * 32,   // A lo
        ((const uint4*)g_f1hi) + (size_t)(b * NN + p0) * 32,   // B hi
        ((const uint4*)g_f1lo) + (size_t)(b * NN + p0) * 32    // B lo
    };
    const int srow0 = tid >> 2, sj = tid & 3;

    float acc[2][8][4];
#pragma unroll
    for (int mi = 0; mi < 2; ++mi)
#pragma unroll
        for (int nj = 0; nj < 8; ++nj)
#pragma unroll
            for (int r = 0; r < 4; ++r) acc[mi][nj][r] = 0.0f;

    uint4 v[8];
#pragma unroll
    for (int t = 0; t < 4; ++t)
#pragma unroll
        for (int s2 = 0; s2 < 2; ++s2) {
            int row = srow0 + s2 * 64;
            v[t * 2 + s2] = __ldg(srcs[t] + (size_t)row * 32 + sj);
        }
#pragma unroll
    for (int t = 0; t < 4; ++t)
#pragma unroll
        for (int s2 = 0; s2 < 2; ++s2) {
            int row = srow0 + s2 * 64;
            *(uint4*)(smem + t * TS + row * 80 + sj * 16) = v[t * 2 + s2];
        }
    __syncthreads();

    const uint32_t lmo = (uint32_t)(((lane & 7) + ((lane >> 3) & 1) * 8) * 80
                                    + ((lane >> 4) & 1) * 16);

    for (int kc = 0; kc < 8; ++kc) {
        if (kc < 7) {
#pragma unroll
            for (int t = 0; t < 4; ++t)
#pragma unroll
                for (int s2 = 0; s2 < 2; ++s2) {
                    int row = srow0 + s2 * 64;
                    v[t * 2 + s2] = __ldg(srcs[t] + (size_t)row * 32 + (kc + 1) * 4 + sj);
                }
        }
        const uint32_t cb = sb + (kc & 1) * BUFSZ;
#pragma unroll
        for (int s = 0; s < 2; ++s) {
            const uint32_t bas = cb + s * 32 + lmo;
            uint32_t ahi[2][4], alo[2][4];
            LDSM4(ahi[0], bas + 0 * TS + (warp_m * 32) * 80);
            LDSM4(ahi[1], bas + 0 * TS + (warp_m * 32 + 16) * 80);
            LDSM4(alo[0], bas + 1 * TS + (warp_m * 32) * 80);
            LDSM4(alo[1], bas + 1 * TS + (warp_m * 32 + 16) * 80);
            uint32_t bhi[4][4], blo[4][4];
#pragma unroll
            for (int nb = 0; nb < 4; ++nb) {
                LDSM4(bhi[nb], bas + 2 * TS + (warp_n * 64 + nb * 16) * 80);
                LDSM4(blo[nb], bas + 3 * TS + (warp_n * 64 + nb * 16) * 80);
            }
#pragma unroll
            for (int term = 0; term < 3; ++term)
#pragma unroll
                for (int mi = 0; mi < 2; ++mi)
#pragma unroll
                    for (int nb = 0; nb < 4; ++nb)
#pragma unroll
                        for (int sub = 0; sub < 2; ++sub) {
                            const int nj = nb * 2 + sub;
                            const uint32_t* af = (term == 2) ? alo[mi] : ahi[mi];
                            const uint32_t* bf = (term == 1) ? blo[nb] : bhi[nb];
                            MMA16816H(acc[mi][nj], af, bf[sub], bf[sub + 2]);
                        }
        }
        if (kc < 7) {
#pragma unroll
            for (int t = 0; t < 4; ++t)
#pragma unroll
                for (int s2 = 0; s2 < 2; ++s2) {
                    int row = srow0 + s2 * 64;
                    *(uint4*)(smem + ((kc + 1) & 1) * BUFSZ + t * TS + row * 80 + sj * 16)
                        = v[t * 2 + s2];
                }
        }
        __syncthreads();
    }

    // ---- spill accumulators to smem (safe: loop ended with sync) ----
    float* accsm = (float*)smem;
#pragma unroll
    for (int mi = 0; mi < 2; ++mi)
#pragma unroll
        for (int nj = 0; nj < 8; ++nj)
#pragma unroll
            for (int r = 0; r < 4; ++r)
                accsm[((mi * 8 + nj) * 4 + r) * 256 + tid] = acc[mi][nj][r];

    // ---- packed constants (exact R13 epilogue form) ----
    u64 C0[HH], C1[HH], CB[HH], CO[HH];
#pragma unroll
    for (int h = 0; h < HH; ++h) {
        C0[h] = pack_dup(__ldg(&W1[2 * h]));
        C1[h] = pack_dup(__ldg(&W1[2 * h + 1]));
        CB[h] = pack_dup(__ldg(&b1[h]));
        CO[h] = pack_dup(0.5f * __ldg(&W2[h]));   // relu via (x+|x|)/2
    }
    const u64 B2v = pack_dup(__ldg(&b2[0]));
    const u64 NH  = pack_dup(-0.5f);
    const u64 N2  = pack_dup(-2.0f);

    const int g = lane >> 2, tig = lane & 3;
    u64 qx2[4], qy2[4], qz2[4], qw2[4];
    const float4* QCp = (const float4*)(smem + OFF_QC);
#pragma unroll
    for (int ridx = 0; ridx < 4; ++ridx) {
        float4 qv = QCp[warp_m * 32 + ridx * 8 + g];
        qx2[ridx] = pack_dup(qv.x); qy2[ridx] = pack_dup(qv.y);
        qz2[ridx] = pack_dup(qv.z); qw2[ridx] = pack_dup(qv.w);
    }
    const float* PX = (const float*)(smem + OFF_PX);
    const float* PY = (const float*)(smem + OFF_PY);
    const float* PZ = (const float*)(smem + OFF_PZ);
    const float* PW = (const float*)(smem + OFF_PW);

    float rowmax[4] = { -CUDART_INF_F, -CUDART_INF_F, -CUDART_INF_F, -CUDART_INF_F };

#pragma unroll
    for (int nj = 0; nj < 8; ++nj) {
        const int cb2 = warp_n * 64 + nj * 8 + 2 * tig;
        u64 px2 = *(const u64*)(PX + cb2);
        u64 py2 = *(const u64*)(PY + cb2);
        u64 pz2 = *(const u64*)(PZ + cb2);
        u64 pw2 = *(const u64*)(PW + cb2);
#pragma unroll
        for (int mi = 0; mi < 2; ++mi)
#pragma unroll
            for (int half = 0; half < 2; ++half) {
                const int ridx = mi * 2 + half;
                const int cidx = (mi * 8 + nj) * 4 + half * 2;
                u64 w1_2 = pack2(accsm[cidx * 256 + tid],
                                 accsm[(cidx + 1) * 256 + tid]);
                u64 s2 = mul2(qx2[ridx], px2);
                s2 = ffma2r(qy2[ridx], py2, s2);
                s2 = ffma2r(qz2[ridx], pz2, s2);
                u64 d2 = add2(qw2[ridx], pw2);
                d2 = ffma2r(N2, s2, d2);
                u64 w2_2 = mul2(add2(d2, d2 & ABSM), NH);
                u64 wv = B2v;
#pragma unroll
                for (int h = 0; h < HH; ++h) {
                    u64 pre = ffma2r(C1[h], w2_2, CB[h]);
                    pre = ffma2r(C0[h], w1_2, pre);
                    wv = ffma2r(CO[h], add2(pre, pre & ABSM), wv);
                }
                float o0, o1;
                unpack2(wv, o0, o1);
                rowmax[ridx] = fmaxf(rowmax[ridx], fmaxf(o0, o1));
                const int row = q0 + warp_m * 32 + mi * 16 + half * 8 + g;
                *(float2*)(out_w + (size_t)(b * NN + row) * NN + p0 + cb2)
                    = make_float2(o0, o1);
            }
    }

    // ---- fused tile-max ----
#pragma unroll
    for (int ridx = 0; ridx < 4; ++ridx) {
        float rm = rowmax[ridx];
        rm = fmaxf(rm, __shfl_xor_sync(0xffffffffu, rm, 1));
        rm = fmaxf(rm, __shfl_xor_sync(0xffffffffu, rm, 2));
        if (tig == 0) {
            const int mi = ridx >> 1, half = ridx & 1;
            const int row = q0 + warp_m * 32 + mi * 16 + half * 8 + g;
            g_tilemax[(size_t)(b * NN + row) * 32 + blockIdx.x * 2 + warp_n] = rm;
        }
    }
}

// ---------------------------------------------------------------
// K3: fused top-8 + softmax + gather. One warp per row.
// ---------------------------------------------------------------
#define TKW 8
__global__ __launch_bounds__(32 * TKW)
void topk_gather_kernel(const float* __restrict__ w,
                        const float* __restrict__ f1,
                        float* __restrict__ out_idx_f,
                        float* __restrict__ out_f)
{
    const int row  = blockIdx.x * TKW + (threadIdx.x >> 5);
    const int lane = threadIdx.x & 31;
    const int b = row >> 11;
    const float4* wr = (const float4*)(w + (size_t)row * NN);

    // ---- threshold: 8th largest tile max ----
    float mv = __ldg(&g_tilemax[(size_t)row * 32 + lane]);
    float thr = mv;
#pragma unroll
    for (int k = 0; k < KTOP; ++k) {
        float bv = mv;
#pragma unroll
        for (int o = 16; o; o >>= 1)
            bv = fmaxf(bv, __shfl_xor_sync(0xffffffffu, bv, o));
        thr = bv;
        unsigned bal = __ballot_sync(0xffffffffu, mv == bv);
        if (lane == __ffs(bal) - 1) mv = -CUDART_INF_F;
    }

    // ---- single filtered pass over the row ----
    float v[KTOP];
    int   id[KTOP];
#pragma unroll
    for (int t = 0; t < KTOP; ++t) { v[t] = -CUDART_INF_F; id[t] = 0x7fffffff; }

#pragma unroll 4
    for (int it = 0; it < 16; ++it) {
        float4 x = __ldg(&wr[it * 32 + lane]);
        if (fmaxf(fmaxf(x.x, x.y), fmaxf(x.z, x.w)) >= thr) {
            int j0 = (it * 32 + lane) * 4;
            float xs[4] = { x.x, x.y, x.z, x.w };
#pragma unroll
            for (int u = 0; u < 4; ++u) {
                float xv = xs[u];
                if (xv >= thr && xv > v[KTOP - 1]) {
                    v[KTOP - 1] = xv; id[KTOP - 1] = j0 + u;
#pragma unroll
                    for (int t = KTOP - 1; t > 0; --t) {
                        if (v[t] > v[t - 1]) {
                            float tv = v[t]; v[t] = v[t - 1]; v[t - 1] = tv;
                            int ti = id[t]; id[t] = id[t - 1]; id[t - 1] = ti;
                        }
                    }
                }
            }
        }
    }

    // ---- merge: 8 warp-argmax rounds; results are warp-uniform ----
    float kv[KTOP];
    int   ki[KTOP];
    int myi = 0;
#pragma unroll
    for (int k = 0; k < KTOP; ++k) {
        float bv = v[0]; int bi = id[0]; int bl = lane;
#pragma unroll
        for (int o = 16; o; o >>= 1) {
            float ov = __shfl_xor_sync(0xffffffffu, bv, o);
            int   oi = __shfl_xor_sync(0xffffffffu, bi, o);
            int   ol = __shfl_xor_sync(0xffffffffu, bl, o);
            if (ov > bv || (ov == bv && oi < bi)) { bv = ov; bi = oi; bl = ol; }
        }
        if (lane == bl) {
#pragma unroll
            for (int t = 0; t < KTOP - 1; ++t) { v[t] = v[t + 1]; id[t] = id[t + 1]; }
            v[KTOP - 1] = -CUDART_INF_F; id[KTOP - 1] = 0x7fffffff;
        }
        kv[k] = bv; ki[k] = bi;
        if (lane == k) myi = bi;
    }
    if (lane < KTOP)
        out_idx_f[(size_t)row * KTOP + lane] = (float)myi;

    // ---- softmax (uniform across lanes; kv sorted desc) ----
    float ws[KTOP];
    float s = 0.0f;
#pragma unroll
    for (int k = 0; k < KTOP; ++k) { ws[k] = expf(kv[k] - kv[0]); s += ws[k]; }
    float invs = 1.0f / s;

    // ---- gather: lane owns dims [lane*8, lane*8+8) = 2 float4 ----
    float4 mxa = make_float4(-CUDART_INF_F, -CUDART_INF_F, -CUDART_INF_F, -CUDART_INF_F);
    float4 mxb = mxa;
    float4 sma = make_float4(0.f, 0.f, 0.f, 0.f);
    float4 smb = sma;
#pragma unroll
    for (int k = 0; k < KTOP; ++k) {
        const float4* fp = (const float4*)(f1 + ((size_t)b * NN + ki[k]) * DD);
        float wk = ws[k] * invs;
        float4 xa = __ldg(fp + 2 * lane);
        float4 xb = __ldg(fp + 2 * lane + 1);
        mxa.x = fmaxf(mxa.x, xa.x); mxa.y = fmaxf(mxa.y, xa.y);
        mxa.z = fmaxf(mxa.z, xa.z); mxa.w = fmaxf(mxa.w, xa.w);
        mxb.x = fmaxf(mxb.x, xb.x); mxb.y = fmaxf(mxb.y, xb.y);
        mxb.z = fmaxf(mxb.z, xb.z); mxb.w = fmaxf(mxb.w, xb.w);
        sma.x = fmaf(wk, xa.x, sma.x); sma.y = fmaf(wk, xa.y, sma.y);
        sma.z = fmaf(wk, xa.z, sma.z); sma.w = fmaf(wk, xa.w, sma.w);
        smb.x = fmaf(wk, xb.x, smb.x); smb.y = fmaf(wk, xb.y, smb.y);
        smb.z = fmaf(wk, xb.z, smb.z); smb.w = fmaf(wk, xb.w, smb.w);
    }
    float4* o = (float4*)(out_f + (size_t)row * (2 * DD));
    o[2 * lane]          = sma;   // weighted, dims [0,256)
    o[2 * lane + 1]      = smb;
    o[64 + 2 * lane]     = mxa;   // max, dims [256,512)
    o[64 + 2 * lane + 1] = mxb;
}

// ---------------------------------------------------------------
extern "C" void kernel_launch(void* const* d_in, const int* in_sizes, int n_in,
                              void* d_out, int out_size)
{
    const float* f1 = (const float*)d_in[0];
    const float* f2 = (const float*)d_in[1];
    const float* p  = (const float*)d_in[2];
    const float* q  = (const float*)d_in[3];
    const float* W1 = (const float*)d_in[4];
    const float* b1 = (const float*)d_in[5];
    const float* W2 = (const float*)d_in[6];
    const float* b2 = (const float*)d_in[7];

    float* out     = (float*)d_out;
    float* out_f   = out;                                   // [B,N,2D]
    float* out_idx = out + (size_t)BB * NN * 2 * DD;        // [B,N,K] (as float)
    float* out_w   = out_idx + (size_t)BB * NN * KTOP;      // [B,N,N]

    cudaFuncSetAttribute(w_kernel, cudaFuncAttributeMaxDynamicSharedMemorySize, SM_TOTAL);

    prep_f1_kernel<<<(BB * NN) / 8, 256>>>(f1);       // launch 0
    prep_f2_kernel<<<(BB * NN) / 8, 256>>>(f2);       // launch 1
    prep_coord_kernel<<<(BB * NN) / 256, 256>>>(p, q);// launch 2

    dim3 g2(NN / 128, NN / 128, BB);
    w_kernel<<<g2, 256, SM_TOTAL>>>(W1, b1, W2, b2, out_w);   // launch 3 (profiled)

    topk_gather_kernel<<<(BB * NN) / TKW, 32 * TKW>>>(out_w, f1, out_idx, out_f);
}

// round 16
// speedup vs baseline: 1.0476x; 1.0476x over previous
#include <cuda_runtime.h>
#include <cuda_fp16.h>
#include <math_constants.h>
#include <cstdint>

#define BB 8
#define NN 2048
#define DD 256
#define HH 16
#define KTOP 8

typedef unsigned long long u64;

// ---- scratch (static device globals; no allocation allowed) ----
__device__ unsigned short g_f1hi[BB * NN * DD];   // fp16 hi of f1n (B)
__device__ unsigned short g_f1lo[BB * NN * DD];   // fp16 lo of f1n (B)
__device__ unsigned short g_f2hi[BB * NN * DD];   // fp16 hi of f2n (A)
__device__ unsigned short g_f2lo[BB * NN * DD];   // fp16 lo of f2n (A)
__device__ float4 g_q4[BB * NN];            // (x,y,z,|q|^2)
__device__ float4 g_p4[BB * NN];            // (x,y,z,|p|^2)
__device__ float  g_tilemax[BB * NN * 64];  // per-row per-32col-tile max of w
__device__ float  g_vals[BB * NN * KTOP];
__device__ int    g_idx [BB * NN * KTOP];

// ======================= helpers =======================
__device__ __forceinline__ uint32_t smem_u32(const void* p) {
    uint32_t a;
    asm("{ .reg .u64 t; cvta.to.shared.u64 t, %1; cvt.u32.u64 %0, t; }"
        : "=r"(a) : "l"(p));
    return a;
}

// ---- packed f32x2 helpers ----
__device__ __forceinline__ u64 pack_dup(float x) {
    u64 r; asm("mov.b64 %0, {%1, %1};" : "=l"(r) : "f"(x)); return r;
}
__device__ __forceinline__ u64 pack2(float lo, float hi) {
    u64 r; asm("mov.b64 %0, {%1, %2};" : "=l"(r) : "f"(lo), "f"(hi)); return r;
}
__device__ __forceinline__ void unpack2(u64 v, float& lo, float& hi) {
    asm("mov.b64 {%0, %1}, %2;" : "=f"(lo), "=f"(hi) : "l"(v));
}
__device__ __forceinline__ u64 ffma2r(u64 a, u64 b, u64 c) {
    u64 d; asm("fma.rn.f32x2 %0, %1, %2, %3;" : "=l"(d) : "l"(a), "l"(b), "l"(c));
    return d;
}
__device__ __forceinline__ u64 mul2(u64 a, u64 b) {
    u64 d; asm("mul.rn.f32x2 %0, %1, %2;" : "=l"(d) : "l"(a), "l"(b)); return d;
}
__device__ __forceinline__ u64 add2(u64 a, u64 b) {
    u64 d; asm("add.rn.f32x2 %0, %1, %2;" : "=l"(d) : "l"(a), "l"(b)); return d;
}
#define ABSM 0x7FFFFFFF7FFFFFFFULL

// ---- legacy tensor-core primitives (sm_80+ baseline PTX) ----
#define LDSM4(R, A) \
    asm volatile("ldmatrix.sync.aligned.m8n8.x4.shared.b16 {%0,%1,%2,%3}, [%4];" \
        : "=r"((R)[0]), "=r"((R)[1]), "=r"((R)[2]), "=r"((R)[3]) : "r"(A))

#define MMA16816H(C, A, B0, B1) \
    asm volatile("mma.sync.aligned.m16n8k16.row.col.f32.f16.f16.f32 " \
        "{%0,%1,%2,%3},{%4,%5,%6,%7},{%8,%9},{%0,%1,%2,%3};" \
        : "+f"((C)[0]), "+f"((C)[1]), "+f"((C)[2]), "+f"((C)[3]) \
        : "r"((A)[0]), "r"((A)[1]), "r"((A)[2]), "r"((A)[3]), "r"(B0), "r"(B1))

// ---------------------------------------------------------------
// K1a/K1b: normalize rows of one tensor to fp16 hi/lo pairs
// ---------------------------------------------------------------
__device__ __forceinline__ void norm_body(const float* __restrict__ src,
                                          unsigned short* dh, unsigned short* dl)
{
    int r = (blockIdx.x * blockDim.x + threadIdx.x) >> 5;
    int lane = threadIdx.x & 31;

    const float4* x = (const float4*)(src + (size_t)r * DD);
    float4 a = x[lane];
    float4 c = x[lane + 32];
    float ss = a.x * a.x + a.y * a.y + a.z * a.z + a.w * a.w
             + c.x * c.x + c.y * c.y + c.z * c.z + c.w * c.w;
#pragma unroll
    for (int o = 16; o; o >>= 1) ss += __shfl_xor_sync(0xffffffffu, ss, o);
    float inv = 1.0f / (sqrtf(ss) + 1e-8f);

    float va[8] = { a.x * inv, a.y * inv, a.z * inv, a.w * inv,
                    c.x * inv, c.y * inv, c.z * inv, c.w * inv };
    unsigned short hi[8], lo[8];
#pragma unroll
    for (int i = 0; i < 8; ++i) {
        __half hh = __float2half_rn(va[i]);
        hi[i] = __half_as_ushort(hh);
        lo[i] = __half_as_ushort(__float2half_rn(va[i] - __half2float(hh)));
    }

    uint2* oh = (uint2*)(dh + (size_t)r * DD);
    uint2* ol = (uint2*)(dl + (size_t)r * DD);
    oh[lane]      = make_uint2((uint32_t)hi[0] | ((uint32_t)hi[1] << 16),
                               (uint32_t)hi[2] | ((uint32_t)hi[3] << 16));
    oh[lane + 32] = make_uint2((uint32_t)hi[4] | ((uint32_t)hi[5] << 16),
                               (uint32_t)hi[6] | ((uint32_t)hi[7] << 16));
    ol[lane]      = make_uint2((uint32_t)lo[0] | ((uint32_t)lo[1] << 16),
                               (uint32_t)lo[2] | ((uint32_t)lo[3] << 16));
    ol[lane + 32] = make_uint2((uint32_t)lo[4] | ((uint32_t)lo[5] << 16),
                               (uint32_t)lo[6] | ((uint32_t)lo[7] << 16));
}

__global__ void prep_f1_kernel(const float* __restrict__ f1)
{ norm_body(f1, g_f1hi, g_f1lo); }

__global__ void prep_f2_kernel(const float* __restrict__ f2)
{ norm_body(f2, g_f2hi, g_f2lo); }

__global__ void prep_coord_kernel(const float* __restrict__ p,
                                  const float* __restrict__ q)
{
    int t = blockIdx.x * blockDim.x + threadIdx.x;
    if (t < BB * NN) {
        float px = p[t * 3 + 0], py = p[t * 3 + 1], pz = p[t * 3 + 2];
        g_p4[t] = make_float4(px, py, pz, px * px + py * py + pz * pz);
        float qx = q[t * 3 + 0], qy = q[t * 3 + 1], qz = q[t * 3 + 2];
        g_q4[t] = make_float4(qx, qy, qz, qx * qx + qy * qy + qz * qz);
    }
}

// ---------------------------------------------------------------
// K2: mma.sync fp16 3-term GEMM, CTA tile 128x64, warp tile 32x32,
//     2 CTAs/SM. MLP constants in smem; no acc spill (cols adjacent
//     in-thread). w values bit-identical to the R13 kernel.
// ---------------------------------------------------------------
#define TSA    10240          // A tile: 128 rows * 80B
#define TSB    5120           // B tile:  64 rows * 80B
#define BUFSZ  30720          // Ahi,Alo,Bhi,Blo
#define OFF_B  20480          // B tiles start within a buffer
#define OFF_QC 61440
#define OFF_PX 63488
#define OFF_PY 63744
#define OFF_PZ 64000
#define OFF_PW 64256
#define OFF_CN 64512          // 65 packed u64 MLP constants
#define SM_TOTAL 65088

__global__ void __launch_bounds__(256, 2)
w_kernel(const float* __restrict__ W1, const float* __restrict__ b1,
         const float* __restrict__ W2, const float* __restrict__ b2,
         float* __restrict__ out_w)
{
    extern __shared__ __align__(1024) unsigned char smem[];
    const uint32_t sb = smem_u32(smem);
    const int tid = threadIdx.x, wid = tid >> 5, lane = tid & 31;
    const int warp_m = wid & 3, warp_n = wid >> 2;
    const int b = blockIdx.z, q0 = blockIdx.y * 128, p0 = blockIdx.x * 64;

    if (tid < 128) {
        ((float4*)(smem + OFF_QC))[tid] = g_q4[b * NN + q0 + tid];
    } else if (tid < 192) {
        int t = tid - 128;
        float4 pv = g_p4[b * NN + p0 + t];
        ((float*)(smem + OFF_PX))[t] = pv.x;
        ((float*)(smem + OFF_PY))[t] = pv.y;
        ((float*)(smem + OFF_PZ))[t] = pv.z;
        ((float*)(smem + OFF_PW))[t] = pv.w;
    }
    if (tid < 16) {
        u64* CN = (u64*)(smem + OFF_CN);
        CN[tid]      = pack_dup(__ldg(&W1[2 * tid]));
        CN[16 + tid] = pack_dup(__ldg(&W1[2 * tid + 1]));
        CN[32 + tid] = pack_dup(__ldg(&b1[tid]));
        CN[48 + tid] = pack_dup(0.5f * __ldg(&W2[tid]));   // relu via (x+|x|)/2
        if (tid == 0) CN[64] = pack_dup(__ldg(&b2[0]));
    }

    const uint4* srcA[2] = {
        ((const uint4*)g_f2hi) + (size_t)(b * NN + q0) * 32,
        ((const uint4*)g_f2lo) + (size_t)(b * NN + q0) * 32
    };
    const uint4* srcB[2] = {
        ((const uint4*)g_f1hi) + (size_t)(b * NN + p0) * 32,
        ((const uint4*)g_f1lo) + (size_t)(b * NN + p0) * 32
    };
    const int srow = tid >> 2, sj = tid & 3;

    float acc[2][4][4];
#pragma unroll
    for (int mi = 0; mi < 2; ++mi)
#pragma unroll
        for (int nj = 0; nj < 4; ++nj)
#pragma unroll
            for (int r = 0; r < 4; ++r) acc[mi][nj][r] = 0.0f;

    uint4 v[6];
    // prologue: chunk 0
#pragma unroll
    for (int t2 = 0; t2 < 2; ++t2) {
#pragma unroll
        for (int s2 = 0; s2 < 2; ++s2)
            v[t2 * 2 + s2] = __ldg(srcA[t2] + (size_t)(srow + s2 * 64) * 32 + sj);
        v[4 + t2] = __ldg(srcB[t2] + (size_t)srow * 32 + sj);
    }
#pragma unroll
    for (int t2 = 0; t2 < 2; ++t2) {
#pragma unroll
        for (int s2 = 0; s2 < 2; ++s2)
            *(uint4*)(smem + t2 * TSA + (srow + s2 * 64) * 80 + sj * 16) = v[t2 * 2 + s2];
        *(uint4*)(smem + OFF_B + t2 * TSB + srow * 80 + sj * 16) = v[4 + t2];
    }
    __syncthreads();

    const uint32_t lmo = (uint32_t)(((lane & 7) + ((lane >> 3) & 1) * 8) * 80
                                    + ((lane >> 4) & 1) * 16);

    for (int kc = 0; kc < 8; ++kc) {
        if (kc < 7) {
#pragma unroll
            for (int t2 = 0; t2 < 2; ++t2) {
#pragma unroll
                for (int s2 = 0; s2 < 2; ++s2)
                    v[t2 * 2 + s2] = __ldg(srcA[t2] + (size_t)(srow + s2 * 64) * 32
                                           + (kc + 1) * 4 + sj);
                v[4 + t2] = __ldg(srcB[t2] + (size_t)srow * 32 + (kc + 1) * 4 + sj);
            }
        }
        const uint32_t cb = sb + (kc & 1) * BUFSZ;
#pragma unroll
        for (int s = 0; s < 2; ++s) {
            const uint32_t bas = cb + s * 32 + lmo;
            uint32_t ahi[2][4], alo[2][4], bhi[2][4], blo[2][4];
#pragma unroll
            for (int mi = 0; mi < 2; ++mi) {
                LDSM4(ahi[mi], bas + (warp_m * 32 + mi * 16) * 80);
                LDSM4(alo[mi], bas + TSA + (warp_m * 32 + mi * 16) * 80);
            }
#pragma unroll
            for (int nb = 0; nb < 2; ++nb) {
                LDSM4(bhi[nb], bas + OFF_B + (warp_n * 32 + nb * 16) * 80);
                LDSM4(blo[nb], bas + OFF_B + TSB + (warp_n * 32 + nb * 16) * 80);
            }
#pragma unroll
            for (int term = 0; term < 3; ++term)
#pragma unroll
                for (int mi = 0; mi < 2; ++mi)
#pragma unroll
                    for (int nb = 0; nb < 2; ++nb)
#pragma unroll
                        for (int sub = 0; sub < 2; ++sub) {
                            const int nj = nb * 2 + sub;
                            const uint32_t* af = (term == 2) ? alo[mi] : ahi[mi];
                            const uint32_t* bf = (term == 1) ? blo[nb] : bhi[nb];
                            MMA16816H(acc[mi][nj], af, bf[sub], bf[sub + 2]);
                        }
        }
        if (kc < 7) {
            const uint32_t nbuf = ((kc + 1) & 1) * BUFSZ;
#pragma unroll
            for (int t2 = 0; t2 < 2; ++t2) {
#pragma unroll
                for (int s2 = 0; s2 < 2; ++s2)
                    *(uint4*)(smem + nbuf + t2 * TSA + (srow + s2 * 64) * 80 + sj * 16)
                        = v[t2 * 2 + s2];
                *(uint4*)(smem + nbuf + OFF_B + t2 * TSB + srow * 80 + sj * 16) = v[4 + t2];
            }
        }
        __syncthreads();
    }

    // ---- epilogue: constants from smem, no acc spill ----
    const u64* CN = (const u64*)(smem + OFF_CN);
    const u64 B2v = CN[64];
    const u64 NH  = pack_dup(-0.5f);
    const u64 N2  = pack_dup(-2.0f);
    const int g = lane >> 2, tig = lane & 3;
    const float* PX = (const float*)(smem + OFF_PX);
    const float* PY = (const float*)(smem + OFF_PY);
    const float* PZ = (const float*)(smem + OFF_PZ);
    const float* PW = (const float*)(smem + OFF_PW);
    const float4* QCp = (const float4*)(smem + OFF_QC);

#pragma unroll
    for (int ridx = 0; ridx < 4; ++ridx) {
        const int mi = ridx >> 1, half = ridx & 1;
        const int lrow = warp_m * 32 + mi * 16 + half * 8 + g;
        float4 qv = QCp[lrow];
        const u64 qx2 = pack_dup(qv.x), qy2 = pack_dup(qv.y);
        const u64 qz2 = pack_dup(qv.z), qw2 = pack_dup(qv.w);

        u64 w1v[4], w2v[4], wv[4];
#pragma unroll
        for (int nj = 0; nj < 4; ++nj) {
            const int cl = warp_n * 32 + nj * 8 + 2 * tig;
            u64 px2 = *(const u64*)(PX + cl);
            u64 py2 = *(const u64*)(PY + cl);
            u64 pz2 = *(const u64*)(PZ + cl);
            u64 pw2 = *(const u64*)(PW + cl);
            w1v[nj] = pack2(acc[mi][nj][half * 2], acc[mi][nj][half * 2 + 1]);
            u64 s2 = mul2(qx2, px2);
            s2 = ffma2r(qy2, py2, s2);
            s2 = ffma2r(qz2, pz2, s2);
            u64 d2 = add2(qw2, pw2);
            d2 = ffma2r(N2, s2, d2);
            w2v[nj] = mul2(add2(d2, d2 & ABSM), NH);
            wv[nj] = B2v;
        }
#pragma unroll
        for (int h = 0; h < HH; ++h) {
            const u64 c0 = CN[h], c1 = CN[16 + h];
            const u64 cbv = CN[32 + h], co = CN[48 + h];
#pragma unroll
            for (int nj = 0; nj < 4; ++nj) {
                u64 pre = ffma2r(c1, w2v[nj], cbv);
                pre = ffma2r(c0, w1v[nj], pre);
                wv[nj] = ffma2r(co, add2(pre, pre & ABSM), wv[nj]);
            }
        }
        const int grow = q0 + lrow;
        float* orow = out_w + (size_t)(b * NN + grow) * NN + p0 + warp_n * 32 + 2 * tig;
        float rm = -CUDART_INF_F;
#pragma unroll
        for (int nj = 0; nj < 4; ++nj) {
            float o0, o1;
            unpack2(wv[nj], o0, o1);
            rm = fmaxf(rm, fmaxf(o0, o1));
            *(float2*)(orow + nj * 8) = make_float2(o0, o1);
        }
        rm = fmaxf(rm, __shfl_xor_sync(0xffffffffu, rm, 1));
        rm = fmaxf(rm, __shfl_xor_sync(0xffffffffu, rm, 2));
        if (tig == 0)
            g_tilemax[(size_t)(b * NN + grow) * 64 + blockIdx.x * 2 + warp_n] = rm;
    }
}

// ---------------------------------------------------------------
// K3: per-row top-8, single streamed pass (tilemax threshold)
// ---------------------------------------------------------------
#define TKW 8
__global__ __launch_bounds__(32 * TKW)
void topk_kernel(const float* __restrict__ w, float* __restrict__ out_idx_f)
{
    const int row  = blockIdx.x * TKW + (threadIdx.x >> 5);
    const int lane = threadIdx.x & 31;
    const float4* wr = (const float4*)(w + (size_t)row * NN);

    // ---- threshold: 8th largest of 32 per-lane maxes of 64 tile maxes ----
    float t0 = __ldg(&g_tilemax[(size_t)row * 64 + lane]);
    float t1 = __ldg(&g_tilemax[(size_t)row * 64 + 32 + lane]);
    float mv = fmaxf(t0, t1);
    float thr = mv;
#pragma unroll
    for (int k = 0; k < KTOP; ++k) {
        float bv = mv;
#pragma unroll
        for (int o = 16; o; o >>= 1)
            bv = fmaxf(bv, __shfl_xor_sync(0xffffffffu, bv, o));
        thr = bv;
        unsigned bal = __ballot_sync(0xffffffffu, mv == bv);
        if (lane == __ffs(bal) - 1) mv = -CUDART_INF_F;
    }

    // ---- single filtered pass over the row ----
    float v[KTOP];
    int   id[KTOP];
#pragma unroll
    for (int t = 0; t < KTOP; ++t) { v[t] = -CUDART_INF_F; id[t] = 0x7fffffff; }

#pragma unroll 4
    for (int it = 0; it < 16; ++it) {
        float4 x = __ldg(&wr[it * 32 + lane]);
        if (fmaxf(fmaxf(x.x, x.y), fmaxf(x.z, x.w)) >= thr) {
            int j0 = (it * 32 + lane) * 4;
            float xs[4] = { x.x, x.y, x.z, x.w };
#pragma unroll
            for (int u = 0; u < 4; ++u) {
                float xv = xs[u];
                if (xv >= thr && xv > v[KTOP - 1]) {
                    v[KTOP - 1] = xv; id[KTOP - 1] = j0 + u;
#pragma unroll
                    for (int t = KTOP - 1; t > 0; --t) {
                        if (v[t] > v[t - 1]) {
                            float tv = v[t]; v[t] = v[t - 1]; v[t - 1] = tv;
                            int ti = id[t]; id[t] = id[t - 1]; id[t - 1] = ti;
                        }
                    }
                }
            }
        }
    }

    // ---- merge: 8 warp-argmax rounds (val desc, idx asc tie-break) ----
#pragma unroll
    for (int k = 0; k < KTOP; ++k) {
        float bv = v[0]; int bi = id[0]; int bl = lane;
#pragma unroll
        for (int o = 16; o; o >>= 1) {
            float ov = __shfl_xor_sync(0xffffffffu, bv, o);
            int   oi = __shfl_xor_sync(0xffffffffu, bi, o);
            int   ol = __shfl_xor_sync(0xffffffffu, bl, o);
            if (ov > bv || (ov == bv && oi < bi)) { bv = ov; bi = oi; bl = ol; }
        }
        if (lane == bl) {
#pragma unroll
            for (int t = 0; t < KTOP - 1; ++t) { v[t] = v[t + 1]; id[t] = id[t + 1]; }
            v[KTOP - 1] = -CUDART_INF_F; id[KTOP - 1] = 0x7fffffff;
        }
        if (lane == 0) {
            g_vals[(size_t)row * KTOP + k] = bv;
            g_idx [(size_t)row * KTOP + k] = bi;
            out_idx_f[(size_t)row * KTOP + k] = (float)bi;
        }
    }
}

// ---------------------------------------------------------------
// K4: softmax + gather; 64 threads/row, float4, precomputed pointers
// ---------------------------------------------------------------
__global__ __launch_bounds__(256)
void gather_kernel(const float* __restrict__ f1, float* __restrict__ out_f)
{
    const int rslot = threadIdx.x >> 6;       // 4 rows per block
    const int row = blockIdx.x * 4 + rslot;
    const int t = threadIdx.x & 63;
    const int b = row >> 11;

    __shared__ float ws[4][KTOP];
    __shared__ const float4* bp[4][KTOP];

    if (t == 0) {
        float e[KTOP];
        float m = g_vals[(size_t)row * KTOP];
        float s = 0.0f;
#pragma unroll
        for (int k = 0; k < KTOP; ++k) {
            e[k] = expf(g_vals[(size_t)row * KTOP + k] - m);
            s += e[k];
        }
        float invs = 1.0f / s;
#pragma unroll
        for (int k = 0; k < KTOP; ++k) {
            ws[rslot][k] = e[k] * invs;
            bp[rslot][k] = (const float4*)(f1 +
                ((size_t)b * NN + g_idx[(size_t)row * KTOP + k]) * DD);
        }
    }
    __syncthreads();

    float4 mx = make_float4(-CUDART_INF_F, -CUDART_INF_F, -CUDART_INF_F, -CUDART_INF_F);
    float4 sm = make_float4(0.f, 0.f, 0.f, 0.f);
#pragma unroll
    for (int k = 0; k < KTOP; ++k) {
        float4 x = __ldg(bp[rslot][k] + t);
        float wk = ws[rslot][k];
        mx.x = fmaxf(mx.x, x.x); mx.y = fmaxf(mx.y, x.y);
        mx.z = fmaxf(mx.z, x.z); mx.w = fmaxf(mx.w, x.w);
        sm.x = fmaf(wk, x.x, sm.x); sm.y = fmaf(wk, x.y, sm.y);
        sm.z = fmaf(wk, x.z, sm.z); sm.w = fmaf(wk, x.w, sm.w);
    }
    float4* o = (float4*)(out_f + (size_t)row * (2 * DD));
    o[t]      = sm;   // weighted first
    o[64 + t] = mx;   // then max
}

// ---------------------------------------------------------------
extern "C" void kernel_launch(void* const* d_in, const int* in_sizes, int n_in,
                              void* d_out, int out_size)
{
    const float* f1 = (const float*)d_in[0];
    const float* f2 = (const float*)d_in[1];
    const float* p  = (const float*)d_in[2];
    const float* q  = (const float*)d_in[3];
    const float* W1 = (const float*)d_in[4];
    const float* b1 = (const float*)d_in[5];
    const float* W2 = (const float*)d_in[6];
    const float* b2 = (const float*)d_in[7];

    float* out     = (float*)d_out;
    float* out_f   = out;                                   // [B,N,2D]
    float* out_idx = out + (size_t)BB * NN * 2 * DD;        // [B,N,K] (as float)
    float* out_w   = out_idx + (size_t)BB * NN * KTOP;      // [B,N,N]

    cudaFuncSetAttribute(w_kernel, cudaFuncAttributeMaxDynamicSharedMemorySize, SM_TOTAL);

    prep_f1_kernel<<<(BB * NN) / 8, 256>>>(f1);        // launch 0
    prep_f2_kernel<<<(BB * NN) / 8, 256>>>(f2);        // launch 1
    prep_coord_kernel<<<(BB * NN) / 256, 256>>>(p, q); // launch 2

    dim3 g2(NN / 64, NN / 128, BB);
    w_kernel<<<g2, 256, SM_TOTAL>>>(W1, b1, W2, b2, out_w);   // launch 3 (profiled)

    topk_kernel<<<(BB * NN) / TKW, 32 * TKW>>>(out_w, out_idx);
    gather_kernel<<<(BB * NN) / 4, 256>>>(f1, out_f);
}